// round 14
// baseline (speedup 1.0000x reference)
#include <cuda_runtime.h>
#include <cuda_fp16.h>
#include <cstdint>

#define Bb 32
#define Nn 1024
#define Tt 32
#define Ff 5
#define Hh 64
#define Rr 5
#define BN (Bb*Nn)
#define NSEQ 64

// Scratch
__device__ float  g_eold[(size_t)BN * Hh];            // 8 MB
__device__ float  g_coef[(size_t)Nn * Nn];            // 4 MB
__device__ float  g_deg[Nn];
__device__ __half g_hist[(size_t)BN * Tt * Hh];       // 128 MB h history

__device__ __forceinline__ float tanha(float x) {
    float y; asm("tanh.approx.f32 %0, %1;" : "=f"(y) : "f"(x)); return y;
}
__device__ __forceinline__ float sigma(float x) {
    return fmaf(0.5f, tanha(0.5f * x), 0.5f);
}
__device__ __forceinline__ uint32_t smem_u32(const void* p) {
    uint32_t a;
    asm("{ .reg .u64 t; cvta.to.shared.u64 t, %1; cvt.u32.u64 %0, t; }" : "=r"(a) : "l"(p));
    return a;
}
__device__ __forceinline__ uint32_t pack_h2(float lo, float hi) {
    __half2 h = __floats2half2_rn(lo, hi);
    return *(uint32_t*)&h;
}

// fp16 MMA: D[16,8] += A[16,16] * B[16,8], f32 accum
#define MMA_F16(D, A, B) \
    asm volatile("mma.sync.aligned.m16n8k16.row.col.f32.f16.f16.f32 " \
        "{%0,%1,%2,%3}, {%4,%5,%6,%7}, {%8,%9}, {%0,%1,%2,%3};" \
        : "+f"((D)[0]), "+f"((D)[1]), "+f"((D)[2]), "+f"((D)[3]) \
        : "r"((A)[0]), "r"((A)[1]), "r"((A)[2]), "r"((A)[3]), \
          "r"((B)[0]), "r"((B)[1]))

#define LDSM4(r, addr) \
    asm volatile("ldmatrix.sync.aligned.m8n8.x4.shared.b16 {%0,%1,%2,%3}, [%4];" \
        : "=r"((r)[0]), "=r"((r)[1]), "=r"((r)[2]), "=r"((r)[3]) : "r"(addr))
#define LDSM4T(r, addr) \
    asm volatile("ldmatrix.sync.aligned.m8n8.x4.trans.shared.b16 {%0,%1,%2,%3}, [%4];" \
        : "=r"((r)[0]), "=r"((r)[1]), "=r"((r)[2]), "=r"((r)[3]) : "r"(addr))

// ---- LSTM smem layout (byte offsets); rows of 88 halves (176B, conflict-free) ----
#define ASTH   88
#define AS0_B  0                            // A buf0 [64][88] half = 11264
#define AS1_B  11264                        // A buf1
#define BS_B   22528                        // B tile [256][88] half = 45056
#define DYN_SMEM (BS_B + 45056)             // 67584 B

// ---- GNN smem layout (byte offsets) ----
#define GJT    64
#define EJH_ST 88
#define SH_ST  72
#define CF_ST  68
#define G_EJ_B 0
#define G_SH_B 11264
#define G_CF_B (11264 + 18432)
#define GNN_SMEM (G_CF_B + 34816)

// ---------------------------------------------------------------------------
// Kernel 1: edge gates
// ---------------------------------------------------------------------------
__global__ __launch_bounds__(256) void prep_kernel(
    const float* __restrict__ A,
    const float* __restrict__ gnn_w,
    const float* __restrict__ gnn_b)
{
    const int i = blockIdx.x;
    const float gw0 = gnn_w[0], gw1 = gnn_w[1], gw2 = gnn_w[2],
                gw3 = gnn_w[3], gw4 = gnn_w[4];
    const float gb = gnn_b[0];
    float degloc = 0.f;
    for (int j = threadIdx.x; j < Nn; j += 256) {
        const float* a = A + ((size_t)i * Nn + j) * Rr;
        float a0 = a[0], a1 = a[1], a2 = a[2], a3 = a[3], a4 = a[4];
        float s = a0 + a1 + a2 + a3 + a4;
        float z = gb + a0 * gw0 + a1 * gw1 + a2 * gw2 + a3 * gw3 + a4 * gw4;
        float w = z > 0.f ? z : 0.2f * z;
        float m = s > 0.f ? 1.f : 0.f;
        g_coef[(size_t)i * Nn + j] = m * w;
        degloc += m;
    }
    __shared__ float red[256];
    red[threadIdx.x] = degloc;
    __syncthreads();
    for (int o = 128; o > 0; o >>= 1) {
        if (threadIdx.x < o) red[threadIdx.x] += red[threadIdx.x + o];
        __syncthreads();
    }
    if (threadIdx.x == 0) g_deg[i] = red[0];
}

// ---------------------------------------------------------------------------
// LSTM phase 1: per m-tile, A + B frags from smem via ldmatrix, fp32 activations.
// Writes h to the NEXT A buffer and to global history. No attention work.
// ---------------------------------------------------------------------------
template<int R>
__device__ __forceinline__ void lstm_phase1(
    uint32_t lm, uint32_t bbb, float (&c_)[16],
    __half* __restrict__ Awr, __half* __restrict__ histT,
    int w, int gq, int tq)
{
#pragma unroll
    for (int mti = 0; mti < 4; mti++) {
        const int mt = (mti + R) & 3;
        float d[4][4];
#pragma unroll
        for (int nt = 0; nt < 4; nt++) {
            d[nt][0] = 0.f; d[nt][1] = 0.f; d[nt][2] = 0.f; d[nt][3] = 0.f;
        }
        const uint32_t mb = lm + (uint32_t)mt * 16 * (ASTH * 2);
#pragma unroll
        for (int kt = 0; kt < 5; kt++) {
            uint32_t a[4], bb[4];
            LDSM4(a, mb + kt * 32);
            LDSM4(bb, bbb + kt * 32);                       // nt0, nt1
            MMA_F16(d[0], a, bb);
            MMA_F16(d[1], a, bb + 2);
            LDSM4(bb, bbb + kt * 32 + 128 * (ASTH * 2));    // nt2, nt3
            MMA_F16(d[2], a, bb);
            MMA_F16(d[3], a, bb + 2);
        }
        float hv[4];
#pragma unroll
        for (int e = 0; e < 4; e++) {
            const int p = mt * 4 + e;
            float gi = d[0][e], gf = d[1][e], gg = d[2][e], go = d[3][e];
            float cn = sigma(gf) * c_[p] + sigma(gi) * tanha(gg);
            c_[p] = cn;
            hv[e] = sigma(go) * tanha(cn);
        }
        // write h pairs: (e0,e1) -> seqr0, (e2,e3) -> seqr0+8
        const int seqr0 = mt * 16 + gq;
        const int jj = w * 8 + 2 * tq;
        __half2 h2a = __floats2half2_rn(hv[0], hv[1]);
        __half2 h2b = __floats2half2_rn(hv[2], hv[3]);
        *(__half2*)(Awr + seqr0 * ASTH + jj) = h2a;
        *(__half2*)(Awr + (seqr0 + 8) * ASTH + jj) = h2b;
        *(__half2*)(histT + (size_t)seqr0 * (Tt * Hh) + jj) = h2a;
        *(__half2*)(histT + (size_t)(seqr0 + 8) * (Tt * Hh) + jj) = h2b;
    }
}

// ---------------------------------------------------------------------------
// Kernel 2: fp16 mma.sync LSTM.  64 seq/CTA, 8 warps, target 3 CTA/SM.
// B tile in smem (ldmatrix per step); h history -> global; 1 barrier/step.
// ---------------------------------------------------------------------------
__global__ __launch_bounds__(256, 3) void lstm_mma_kernel(
    const float* __restrict__ x,
    const float* __restrict__ Wih,
    const float* __restrict__ Whh,
    const float* __restrict__ bih,
    const float* __restrict__ bhh)
{
    extern __shared__ char smc[];
    __half* As0 = (__half*)(smc + AS0_B);
    __half* As1 = (__half*)(smc + AS1_B);
    __half* Bs  = (__half*)(smc + BS_B);

    const int tid  = threadIdx.x;
    const int w    = tid >> 5, lane = tid & 31;
    const int gq   = lane >> 2;
    const int tq   = lane & 3;
    const size_t seq0 = (size_t)blockIdx.x * NSEQ;

    // zero both A tiles
    {
        uint4 z4 = {0u,0u,0u,0u};
        uint4* ap = (uint4*)As0;
        for (int i = tid; i < 2 * NSEQ * ASTH * 2 / 16; i += 256) ap[i] = z4;
    }
    // fill B tile: row g = tid
    {
        __half* brow = Bs + tid * ASTH;
        const float* wr = Whh + (size_t)tid * Hh;
#pragma unroll 4
        for (int k = 0; k < 64; k += 2)
            *(__half2*)(brow + k) = __floats2half2_rn(wr[k], wr[k + 1]);
#pragma unroll
        for (int f = 0; f < Ff; f++) brow[64 + f] = __float2half(Wih[tid * Ff + f]);
        brow[69] = __float2half(bih[tid] + bhh[tid]);
#pragma unroll
        for (int k = 70; k < ASTH; k++) brow[k] = __float2half(0.f);
    }
    __syncthreads();
    const float* xrow = x + (seq0 + tid) * (Tt * Ff);
    if (tid < NSEQ) {
        As0[tid * ASTH + 69] = __float2half(1.0f);
        As1[tid * ASTH + 69] = __float2half(1.0f);
#pragma unroll
        for (int f = 0; f < Ff; f++)
            As0[tid * ASTH + 64 + f] = __float2half(xrow[f]);
    }
    __syncthreads();

    float c_[16];
#pragma unroll
    for (int p = 0; p < 16; p++) c_[p] = 0.f;

    const uint32_t as_u = smem_u32(As0);
    const uint32_t lm0 = as_u + (uint32_t)(lane & 15) * (ASTH * 2)
                       + (uint32_t)((lane >> 4) * 16);
    const uint32_t lm1 = lm0 + (AS1_B - AS0_B);
    // B ldmatrix lane base: rows = nt*64 + w*8 + (lane&7); lanes 0-15 -> nt0, 16-31 -> nt1
    const uint32_t bs_u = smem_u32(Bs);
    const uint32_t bbb = bs_u
        + (uint32_t)(w * 8 + (lane & 7) + (lane >> 4) * 64) * (ASTH * 2)
        + (uint32_t)((lane >> 3) & 1) * 16;
    const int rot = w & 3;
    __half* histB = g_hist + (size_t)seq0 * (Tt * Hh);

    for (int t = 0; t < Tt; t++) {
        const uint32_t lm_cur = (t & 1) ? lm1 : lm0;
        __half* Awr = (t & 1) ? As0 : As1;
        __half* histT = histB + (size_t)t * Hh;

        // prefetch x_{t+1} (latency hidden behind phase 1)
        float xv0 = 0.f, xv1 = 0.f, xv2 = 0.f, xv3 = 0.f, xv4 = 0.f;
        if (t < Tt - 1 && tid < NSEQ) {
            const float* xr = xrow + (t + 1) * Ff;
            xv0 = xr[0]; xv1 = xr[1]; xv2 = xr[2]; xv3 = xr[3]; xv4 = xr[4];
        }

        switch (rot) {
            case 0: lstm_phase1<0>(lm_cur, bbb, c_, Awr, histT, w, gq, tq); break;
            case 1: lstm_phase1<1>(lm_cur, bbb, c_, Awr, histT, w, gq, tq); break;
            case 2: lstm_phase1<2>(lm_cur, bbb, c_, Awr, histT, w, gq, tq); break;
            default: lstm_phase1<3>(lm_cur, bbb, c_, Awr, histT, w, gq, tq); break;
        }

        if (t < Tt - 1 && tid < NSEQ) {
            __half* ax = Awr + tid * ASTH + 64;
            ax[0] = __float2half(xv0); ax[1] = __float2half(xv1);
            ax[2] = __float2half(xv2); ax[3] = __float2half(xv3);
            ax[4] = __float2half(xv4);
        }
        __syncthreads();
    }
}

// ---------------------------------------------------------------------------
// Kernel 2b: temporal attention over h history.  Warp handles 8 seqs.
// lane l owns h columns (2l, 2l+1); scores via shfl tree; fp32 softmax.
// ---------------------------------------------------------------------------
__global__ __launch_bounds__(256) void attn_kernel(
    const float* __restrict__ attn_w,
    const float* __restrict__ attn_b)
{
    __shared__ float swn[8][33];
    const int wid = threadIdx.x >> 5, lane = threadIdx.x & 31;
    const int seqbase = (blockIdx.x * 8 + wid) * 8;   // grid 512 x 8 warps x 8 seqs
    const float aw0 = attn_w[2 * lane], aw1 = attn_w[2 * lane + 1];
    const float ab = attn_b[0];

    for (int sq = 0; sq < 8; sq++) {
        const int seq = seqbase + sq;
        const __half2* hp = (const __half2*)(g_hist + (size_t)seq * (Tt * Hh)) + lane;
        __half2 hv[Tt];
        float v[Tt];
#pragma unroll
        for (int t = 0; t < Tt; t++) hv[t] = hp[t * 32];
#pragma unroll
        for (int t = 0; t < Tt; t++) {
            float2 f2 = __half22float2(hv[t]);
            v[t] = f2.x * aw0 + f2.y * aw1;
        }
#pragma unroll
        for (int o = 16; o > 0; o >>= 1) {
#pragma unroll
            for (int t = 0; t < Tt; t++)
                v[t] += __shfl_xor_sync(0xffffffffu, v[t], o);
        }
        // lane t computes softmax numerator for timestep t
        float e = __expf(tanha(v[lane] + ab));
        float Z = e;
#pragma unroll
        for (int o = 16; o > 0; o >>= 1) Z += __shfl_xor_sync(0xffffffffu, Z, o);
        swn[wid][lane] = e / Z;
        __syncwarp();
        float a0 = 0.f, a1 = 0.f;
#pragma unroll
        for (int t = 0; t < Tt; t++) {
            float wn = swn[wid][t];
            float2 f2 = __half22float2(hv[t]);
            a0 = fmaf(wn, f2.x, a0);
            a1 = fmaf(wn, f2.y, a1);
        }
        float* eo = g_eold + (size_t)seq * Hh + 2 * lane;
        eo[0] = a0; eo[1] = a1;
    }
}

// ---------------------------------------------------------------------------
// Kernel 3: GNN, fp16 MMA + ldmatrix (round-12, passing)
// ---------------------------------------------------------------------------
__global__ __launch_bounds__(256, 2) void gnn_mma_kernel(
    const float* __restrict__ pred_w,
    const float* __restrict__ pred_b,
    float* __restrict__ out)
{
    extern __shared__ char gsc[];
    __half* Ejs = (__half*)(gsc + G_EJ_B);
    __half* Sh  = (__half*)(gsc + G_SH_B);
    float*  CF  = (float*)(gsc + G_CF_B);

    const int tid = threadIdx.x;
    const int w = tid >> 5, lane = tid & 31;
    const int gq = lane >> 2, tq = lane & 3;
    const int b  = blockIdx.y;
    const int i0 = blockIdx.x * 128;
    const float* eob = g_eold + (size_t)b * Nn * Hh;

    uint32_t ae[4][4];
    {
        const float* r0 = eob + (size_t)(i0 + w * 16 + gq) * Hh;
        const float* r1 = r0 + 8 * Hh;
#pragma unroll
        for (int kt = 0; kt < 4; kt++) {
            int k0 = kt * 16 + 2 * tq;
            ae[kt][0] = pack_h2(r0[k0],     r0[k0 + 1]);
            ae[kt][1] = pack_h2(r1[k0],     r1[k0 + 1]);
            ae[kt][2] = pack_h2(r0[k0 + 8], r0[k0 + 9]);
            ae[kt][3] = pack_h2(r1[k0 + 8], r1[k0 + 9]);
        }
    }
    float d2[8][4];
#pragma unroll
    for (int nt = 0; nt < 8; nt++) { d2[nt][0]=0.f; d2[nt][1]=0.f; d2[nt][2]=0.f; d2[nt][3]=0.f; }

    const uint32_t ej_u = smem_u32(Ejs);
    const uint32_t sh_u = smem_u32(Sh);
    const int lr = lane & 7, lt = lane >> 3;
    const uint32_t b1_base = ej_u + (uint32_t)lr * (EJH_ST * 2) + (uint32_t)lt * 16;
    const uint32_t a2_base = sh_u
        + (uint32_t)(w * 16 + lr + (lt & 1) * 8) * (SH_ST * 2) + (uint32_t)(lt >> 1) * 16;
    const uint32_t b2_base = ej_u
        + (uint32_t)(lr + (lt & 1) * 8) * (EJH_ST * 2) + (uint32_t)(lt >> 1) * 16;

    for (int j0 = 0; j0 < Nn; j0 += GJT) {
        __syncthreads();
        {
            int j = tid >> 2, qq = tid & 3;
            const float4* src = (const float4*)(eob + (size_t)(j0 + j) * Hh + qq * 16);
            float4 v0 = src[0], v1 = src[1], v2 = src[2], v3 = src[3];
            __half2* dst = (__half2*)(Ejs + j * EJH_ST + qq * 16);
            dst[0] = __floats2half2_rn(v0.x, v0.y);
            dst[1] = __floats2half2_rn(v0.z, v0.w);
            dst[2] = __floats2half2_rn(v1.x, v1.y);
            dst[3] = __floats2half2_rn(v1.z, v1.w);
            dst[4] = __floats2half2_rn(v2.x, v2.y);
            dst[5] = __floats2half2_rn(v2.z, v2.w);
            dst[6] = __floats2half2_rn(v3.x, v3.y);
            dst[7] = __floats2half2_rn(v3.z, v3.w);
        }
        for (int idx = tid; idx < 128 * 16; idx += 256) {
            int i = idx >> 4, jq = idx & 15;
            *(float4*)(CF + i * CF_ST + jq * 4) =
                *(const float4*)(g_coef + (size_t)(i0 + i) * Nn + j0 + jq * 4);
        }
        __syncthreads();

        float d1[8][4];
#pragma unroll
        for (int nt = 0; nt < 8; nt++) { d1[nt][0]=0.f; d1[nt][1]=0.f; d1[nt][2]=0.f; d1[nt][3]=0.f; }
#pragma unroll
        for (int ktp = 0; ktp < 2; ktp++) {
#pragma unroll
            for (int nt = 0; nt < 8; nt++) {
                uint32_t bb[4];
                LDSM4(bb, b1_base + (uint32_t)nt * 8 * (EJH_ST * 2) + (uint32_t)ktp * 64);
                MMA_F16(d1[nt], ae[ktp * 2],     bb);
                MMA_F16(d1[nt], ae[ktp * 2 + 1], bb + 2);
            }
        }
        {
            const float* c0p = CF + (w * 16 + gq) * CF_ST;
            const float* c1p = c0p + 8 * CF_ST;
            __half* s0p = Sh + (w * 16 + gq) * SH_ST;
            __half* s1p = s0p + 8 * SH_ST;
#pragma unroll
            for (int nt = 0; nt < 8; nt++) {
                int cc = nt * 8 + 2 * tq;
                float2 c0 = *(const float2*)(c0p + cc);
                float2 c1 = *(const float2*)(c1p + cc);
                *(__half2*)(s0p + cc) = __floats2half2_rn(d1[nt][0] * c0.x, d1[nt][1] * c0.y);
                *(__half2*)(s1p + cc) = __floats2half2_rn(d1[nt][2] * c1.x, d1[nt][3] * c1.y);
            }
        }
        __syncwarp();

#pragma unroll
        for (int ktj = 0; ktj < 4; ktj++) {
            uint32_t aa[4];
            LDSM4(aa, a2_base + (uint32_t)ktj * 32);
#pragma unroll
            for (int ntp = 0; ntp < 4; ntp++) {
                uint32_t bb[4];
                LDSM4T(bb, b2_base + (uint32_t)ktj * 16 * (EJH_ST * 2) + (uint32_t)ntp * 32);
                MMA_F16(d2[ntp * 2],     aa, bb);
                MMA_F16(d2[ntp * 2 + 1], aa, bb + 2);
            }
        }
    }

    const int i_a = i0 + w * 16 + gq;
    const int i_b = i_a + 8;
    const float inv0 = 1.0f / g_deg[i_a];
    const float inv1 = 1.0f / g_deg[i_b];
    float p0 = 0.f, p1 = 0.f;
#pragma unroll
    for (int kt = 0; kt < 4; kt++) {
        int k0 = kt * 16 + 2 * tq;
        float wa = pred_w[k0], wb = pred_w[k0 + 1];
        float wc = pred_w[k0 + 8], wd = pred_w[k0 + 9];
        float2 v;
        v = __half22float2(*(__half2*)&ae[kt][0]); p0 = fmaf(v.x, wa, fmaf(v.y, wb, p0));
        v = __half22float2(*(__half2*)&ae[kt][2]); p0 = fmaf(v.x, wc, fmaf(v.y, wd, p0));
        v = __half22float2(*(__half2*)&ae[kt][1]); p1 = fmaf(v.x, wa, fmaf(v.y, wb, p1));
        v = __half22float2(*(__half2*)&ae[kt][3]); p1 = fmaf(v.x, wc, fmaf(v.y, wd, p1));
    }
#pragma unroll
    for (int nt = 0; nt < 8; nt++) {
        float wA = pred_w[64 + nt * 8 + 2 * tq];
        float wB = pred_w[64 + nt * 8 + 2 * tq + 1];
        p0 = fmaf(d2[nt][0] * inv0, wA, p0);
        p0 = fmaf(d2[nt][1] * inv0, wB, p0);
        p1 = fmaf(d2[nt][2] * inv1, wA, p1);
        p1 = fmaf(d2[nt][3] * inv1, wB, p1);
    }
    p0 += __shfl_xor_sync(0xffffffffu, p0, 1);
    p0 += __shfl_xor_sync(0xffffffffu, p0, 2);
    p1 += __shfl_xor_sync(0xffffffffu, p1, 1);
    p1 += __shfl_xor_sync(0xffffffffu, p1, 2);
    if (tq == 0) {
        out[(size_t)b * Nn + i_a] = p0 + pred_b[0];
        out[(size_t)b * Nn + i_b] = p1 + pred_b[0];
    }
}

// ---------------------------------------------------------------------------
extern "C" void kernel_launch(void* const* d_in, const int* in_sizes, int n_in,
                              void* d_out, int out_size)
{
    const float* x      = (const float*)d_in[0];
    const float* A      = (const float*)d_in[1];
    const float* Wih    = (const float*)d_in[2];
    const float* Whh    = (const float*)d_in[3];
    const float* bih    = (const float*)d_in[4];
    const float* bhh    = (const float*)d_in[5];
    const float* attn_w = (const float*)d_in[6];
    const float* attn_b = (const float*)d_in[7];
    const float* gnn_w  = (const float*)d_in[8];
    const float* gnn_b  = (const float*)d_in[9];
    const float* pred_w = (const float*)d_in[10];
    const float* pred_b = (const float*)d_in[11];
    float* out = (float*)d_out;

    cudaFuncSetAttribute(lstm_mma_kernel,
                         cudaFuncAttributeMaxDynamicSharedMemorySize, DYN_SMEM);
    cudaFuncSetAttribute(gnn_mma_kernel,
                         cudaFuncAttributeMaxDynamicSharedMemorySize, GNN_SMEM);

    lstm_mma_kernel<<<BN / NSEQ, 256, DYN_SMEM>>>(x, Wih, Whh, bih, bhh);
    attn_kernel<<<512, 256>>>(attn_w, attn_b);
    prep_kernel<<<Nn, 256>>>(A, gnn_w, gnn_b);
    gnn_mma_kernel<<<dim3(Nn / 128, Bb), 256, GNN_SMEM>>>(pred_w, pred_b, out);
}

// round 15
// speedup vs baseline: 1.5248x; 1.5248x over previous
#include <cuda_runtime.h>
#include <cuda_fp16.h>
#include <cstdint>

#define Bb 32
#define Nn 1024
#define Tt 32
#define Ff 5
#define Hh 64
#define Rr 5
#define BN (Bb*Nn)
#define NSEQ 64

// Scratch
__device__ float g_eold[(size_t)BN * Hh];
__device__ float g_coef[(size_t)Nn * Nn];
__device__ float g_deg[Nn];

__device__ __forceinline__ float tanha(float x) {
    float y; asm("tanh.approx.f32 %0, %1;" : "=f"(y) : "f"(x)); return y;
}
__device__ __forceinline__ float sigma(float x) {
    return fmaf(0.5f, tanha(0.5f * x), 0.5f);
}
__device__ __forceinline__ uint32_t smem_u32(const void* p) {
    uint32_t a;
    asm("{ .reg .u64 t; cvta.to.shared.u64 t, %1; cvt.u32.u64 %0, t; }" : "=r"(a) : "l"(p));
    return a;
}
__device__ __forceinline__ uint32_t pack_h2(float lo, float hi) {
    __half2 h = __floats2half2_rn(lo, hi);
    return *(uint32_t*)&h;
}

// fp16 MMA: D[16,8] += A[16,16] * B[16,8], f32 accum
#define MMA_F16(D, A, B) \
    asm volatile("mma.sync.aligned.m16n8k16.row.col.f32.f16.f16.f32 " \
        "{%0,%1,%2,%3}, {%4,%5,%6,%7}, {%8,%9}, {%0,%1,%2,%3};" \
        : "+f"((D)[0]), "+f"((D)[1]), "+f"((D)[2]), "+f"((D)[3]) \
        : "r"((A)[0]), "r"((A)[1]), "r"((A)[2]), "r"((A)[3]), \
          "r"((B)[0]), "r"((B)[1]))

#define LDSM4(r, addr) \
    asm volatile("ldmatrix.sync.aligned.m8n8.x4.shared.b16 {%0,%1,%2,%3}, [%4];" \
        : "=r"((r)[0]), "=r"((r)[1]), "=r"((r)[2]), "=r"((r)[3]) : "r"(addr))
#define LDSM4T(r, addr) \
    asm volatile("ldmatrix.sync.aligned.m8n8.x4.trans.shared.b16 {%0,%1,%2,%3}, [%4];" \
        : "=r"((r)[0]), "=r"((r)[1]), "=r"((r)[2]), "=r"((r)[3]) : "r"(addr))

// ---- LSTM smem layout (byte offsets); A row = 88 halves ----
#define ASTH   88
#define AS0_B  0
#define AS1_B  11264
#define XH_B   22528
#define SP_B   (XH_B + 20480)
#define WN_B   (SP_B + 2048)
#define AW_B   (WN_B + 256)
#define DYN_SMEM (AW_B + 256)

// ---- GNN smem layout (byte offsets) ----
#define GJT    64
#define EJH_ST 88
#define SH_ST  72
#define CF_ST  68
#define G_EJ_B 0
#define G_SH_B 11264
#define G_CF_B (11264 + 18432)
#define GNN_SMEM (G_CF_B + 34816)

// ---------------------------------------------------------------------------
// LSTM phase 1: MMA + fp32 activations (round-12, validated)
// ---------------------------------------------------------------------------
template<int R>
__device__ __forceinline__ void lstm_phase1(
    uint32_t lm_off, const uint32_t (&bf)[4][5][2], float (&c_)[16], float (&hr)[16])
{
#pragma unroll
    for (int mti = 0; mti < 4; mti++) {
        const int mt = (mti + R) & 3;
        float d[4][4];
#pragma unroll
        for (int nt = 0; nt < 4; nt++) {
            d[nt][0] = 0.f; d[nt][1] = 0.f; d[nt][2] = 0.f; d[nt][3] = 0.f;
        }
        const uint32_t mb = lm_off + (uint32_t)mt * 16 * (ASTH * 2);
#pragma unroll
        for (int kt = 0; kt < 5; kt++) {
            uint32_t a[4];
            LDSM4(a, mb + kt * 32);
#pragma unroll
            for (int nt = 0; nt < 4; nt++)
                MMA_F16(d[nt], a, bf[nt][kt]);
        }
#pragma unroll
        for (int e = 0; e < 4; e++) {
            const int p = mt * 4 + e;
            float gi = d[0][e], gf = d[1][e], gg = d[2][e], go = d[3][e];
            float cn = sigma(gf) * c_[p] + sigma(gi) * tanha(gg);
            c_[p] = cn;
            hr[p] = sigma(go) * tanha(cn);
        }
    }
}

// ---------------------------------------------------------------------------
// Kernel 1: fp16 mma.sync LSTM + attention, with fused edge-gate prep.
// 64 seq/CTA, 8 warps, 2 CTA/SM.  Each CTA also computes coef rows
// {2*bid, 2*bid+1} + deg (prep fused into the latency-bound prologue).
// ---------------------------------------------------------------------------
__global__ __launch_bounds__(256, 2) void lstm_mma_kernel(
    const float* __restrict__ x,
    const float* __restrict__ Wih,
    const float* __restrict__ Whh,
    const float* __restrict__ bih,
    const float* __restrict__ bhh,
    const float* __restrict__ attn_w,
    const float* __restrict__ attn_b,
    const float* __restrict__ Ag,
    const float* __restrict__ gnn_w,
    const float* __restrict__ gnn_b)
{
    extern __shared__ char smc[];
    __half* As0 = (__half*)(smc + AS0_B);
    __half* As1 = (__half*)(smc + AS1_B);
    __half* xh  = (__half*)(smc + XH_B);
    float*  SP  = (float*)(smc + SP_B);
    float*  WN  = (float*)(smc + WN_B);
    float*  AW  = (float*)(smc + AW_B);

    const int tid  = threadIdx.x;
    const int w    = tid >> 5, lane = tid & 31;
    const int gq   = lane >> 2;
    const int tq   = lane & 3;
    const size_t seq0 = (size_t)blockIdx.x * NSEQ;

    // ---- fused prep: coef rows r0, r0+1 (math identical to old prep_kernel) ----
    {
        const int r0 = blockIdx.x * 2;
        const float gw0 = gnn_w[0], gw1 = gnn_w[1], gw2 = gnn_w[2],
                    gw3 = gnn_w[3], gw4 = gnn_w[4];
        const float gb = gnn_b[0];
        float dl0 = 0.f, dl1 = 0.f;
        for (int j = tid; j < Nn; j += 256) {
            const float* a0 = Ag + ((size_t)r0 * Nn + j) * Rr;
            const float* a1 = a0 + (size_t)Nn * Rr;
            {
                float b0 = a0[0], b1 = a0[1], b2 = a0[2], b3 = a0[3], b4 = a0[4];
                float s = b0 + b1 + b2 + b3 + b4;
                float z = gb + b0 * gw0 + b1 * gw1 + b2 * gw2 + b3 * gw3 + b4 * gw4;
                float wv = z > 0.f ? z : 0.2f * z;
                float m = s > 0.f ? 1.f : 0.f;
                g_coef[(size_t)r0 * Nn + j] = m * wv;
                dl0 += m;
            }
            {
                float b0 = a1[0], b1 = a1[1], b2 = a1[2], b3 = a1[3], b4 = a1[4];
                float s = b0 + b1 + b2 + b3 + b4;
                float z = gb + b0 * gw0 + b1 * gw1 + b2 * gw2 + b3 * gw3 + b4 * gw4;
                float wv = z > 0.f ? z : 0.2f * z;
                float m = s > 0.f ? 1.f : 0.f;
                g_coef[(size_t)(r0 + 1) * Nn + j] = m * wv;
                dl1 += m;
            }
        }
        SP[tid] = dl0;
        SP[256 + tid] = dl1;
    }

    // stage x -> half [t][seq][f]
    {
        const float* xg = x + seq0 * (Tt * Ff);
        for (int i = tid; i < NSEQ * Tt * Ff; i += 256) {
            int s = i / (Tt * Ff);
            int r = i - s * (Tt * Ff);
            int t = r / Ff, f = r - t * Ff;
            xh[(t * NSEQ + s) * Ff + f] = __float2half(xg[i]);
        }
    }
    // zero both A tiles
    {
        uint4 z4 = {0u,0u,0u,0u};
        uint4* ap = (uint4*)As0;
        for (int i = tid; i < 2 * NSEQ * ASTH * 2 / 16; i += 256) ap[i] = z4;
    }
    __syncthreads();

    // ---- prep deg reduction (SP free until main loop) ----
    for (int o = 128; o > 0; o >>= 1) {
        if (tid < o) {
            SP[tid] += SP[tid + o];
            SP[256 + tid] += SP[256 + tid + o];
        }
        __syncthreads();
    }
    if (tid == 0) {
        g_deg[blockIdx.x * 2]     = SP[0];
        g_deg[blockIdx.x * 2 + 1] = SP[256];
    }

    if (tid < NSEQ) {
        As0[tid * ASTH + 69] = __float2half(1.0f);
        As1[tid * ASTH + 69] = __float2half(1.0f);
        const __half* xr = xh + tid * Ff;
#pragma unroll
        for (int f = 0; f < Ff; f++) As0[tid * ASTH + 64 + f] = xr[f];
    }
    if (tid < 64) AW[tid] = attn_w[tid];

    // persistent B fragments: bf[nt][kt][2], gate = nt*64 + w*8 + gq, K=80
    uint32_t bf[4][5][2];
#pragma unroll
    for (int nt = 0; nt < 4; nt++) {
        const int g = nt * 64 + w * 8 + gq;
        const float bias_g = bih[g] + bhh[g];
#pragma unroll
        for (int kt = 0; kt < 5; kt++) {
#pragma unroll
            for (int hb = 0; hb < 2; hb++) {
                int k0 = kt * 16 + 2 * tq + hb * 8;
                float v0, v1;
                {
                    int k = k0;
                    if (k < 64)       v0 = Whh[g * Hh + k];
                    else if (k < 69)  v0 = Wih[g * Ff + (k - 64)];
                    else if (k == 69) v0 = bias_g;
                    else              v0 = 0.f;
                }
                {
                    int k = k0 + 1;
                    if (k < 64)       v1 = Whh[g * Hh + k];
                    else if (k < 69)  v1 = Wih[g * Ff + (k - 64)];
                    else if (k == 69) v1 = bias_g;
                    else              v1 = 0.f;
                }
                bf[nt][kt][hb] = pack_h2(v0, v1);
            }
        }
    }
    __syncthreads();

    float c_[16], acc_[16], hr[16];
#pragma unroll
    for (int p = 0; p < 16; p++) { c_[p] = 0.f; acc_[p] = 0.f; }
    float Z = 0.f;
    const float ab0 = attn_b[0];
    const float awA = AW[w * 8 + 2 * tq];
    const float awB = AW[w * 8 + 2 * tq + 1];

    const uint32_t as_u = smem_u32(As0);
    const uint32_t lm0 = as_u + (uint32_t)(lane & 15) * (ASTH * 2)
                       + (uint32_t)((lane >> 4) * 16);
    const uint32_t lm1 = lm0 + (AS1_B - AS0_B);
    const int rot = w & 3;

    for (int t = 0; t < Tt; t++) {
        const uint32_t lm_cur = (t & 1) ? lm1 : lm0;
        __half* Awr = (t & 1) ? As0 : As1;

        switch (rot) {
            case 0: lstm_phase1<0>(lm_cur, bf, c_, hr); break;
            case 1: lstm_phase1<1>(lm_cur, bf, c_, hr); break;
            case 2: lstm_phase1<2>(lm_cur, bf, c_, hr); break;
            default: lstm_phase1<3>(lm_cur, bf, c_, hr); break;
        }

#pragma unroll
        for (int mt = 0; mt < 4; mt++) {
#pragma unroll
            for (int pr = 0; pr < 2; pr++) {
                const int p = mt * 4 + pr * 2;
                const int seqr = mt * 16 + gq + pr * 8;
                *(__half2*)(Awr + seqr * ASTH + w * 8 + 2 * tq) =
                    __floats2half2_rn(hr[p], hr[p + 1]);
            }
        }
        if (t < Tt - 1 && tid < NSEQ) {
            const __half* xr = xh + ((t + 1) * NSEQ + tid) * Ff;
#pragma unroll
            for (int f = 0; f < Ff; f++) Awr[tid * ASTH + 64 + f] = xr[f];
        }
#pragma unroll
        for (int mt = 0; mt < 4; mt++) {
#pragma unroll
            for (int pr = 0; pr < 2; pr++) {
                float v = hr[mt * 4 + pr * 2] * awA + hr[mt * 4 + pr * 2 + 1] * awB;
                v += __shfl_xor_sync(0xffffffffu, v, 1);
                v += __shfl_xor_sync(0xffffffffu, v, 2);
                if (tq == 0) SP[w * NSEQ + mt * 16 + gq + pr * 8] = v;
            }
        }
        __syncthreads();
        if (tid < NSEQ) {
            float s = ab0;
#pragma unroll
            for (int ww = 0; ww < 8; ww++) s += SP[ww * NSEQ + tid];
            float e = __expf(tanha(s));
            Z += e;
            WN[tid] = e;
        }
        __syncthreads();
#pragma unroll
        for (int p = 0; p < 16; p++) {
            const int mt = p >> 2, pr = (p >> 1) & 1;
            acc_[p] = fmaf(WN[mt * 16 + gq + pr * 8], hr[p], acc_[p]);
        }
    }

    if (tid < NSEQ) WN[tid] = 1.0f / Z;
    __syncthreads();
#pragma unroll
    for (int p = 0; p < 16; p++) {
        const int mt = p >> 2, pr = (p >> 1) & 1, pc = p & 1;
        const int seqr = mt * 16 + gq + pr * 8;
        const int j = w * 8 + 2 * tq + pc;
        g_eold[(seq0 + seqr) * Hh + j] = acc_[p] * WN[seqr];
    }
}

// ---------------------------------------------------------------------------
// Kernel 2: GNN, fp16 MMA + ldmatrix (round-12, passing)
// ---------------------------------------------------------------------------
__global__ __launch_bounds__(256, 2) void gnn_mma_kernel(
    const float* __restrict__ pred_w,
    const float* __restrict__ pred_b,
    float* __restrict__ out)
{
    extern __shared__ char gsc[];
    __half* Ejs = (__half*)(gsc + G_EJ_B);
    __half* Sh  = (__half*)(gsc + G_SH_B);
    float*  CF  = (float*)(gsc + G_CF_B);

    const int tid = threadIdx.x;
    const int w = tid >> 5, lane = tid & 31;
    const int gq = lane >> 2, tq = lane & 3;
    const int b  = blockIdx.y;
    const int i0 = blockIdx.x * 128;
    const float* eob = g_eold + (size_t)b * Nn * Hh;

    uint32_t ae[4][4];
    {
        const float* r0 = eob + (size_t)(i0 + w * 16 + gq) * Hh;
        const float* r1 = r0 + 8 * Hh;
#pragma unroll
        for (int kt = 0; kt < 4; kt++) {
            int k0 = kt * 16 + 2 * tq;
            ae[kt][0] = pack_h2(r0[k0],     r0[k0 + 1]);
            ae[kt][1] = pack_h2(r1[k0],     r1[k0 + 1]);
            ae[kt][2] = pack_h2(r0[k0 + 8], r0[k0 + 9]);
            ae[kt][3] = pack_h2(r1[k0 + 8], r1[k0 + 9]);
        }
    }
    float d2[8][4];
#pragma unroll
    for (int nt = 0; nt < 8; nt++) { d2[nt][0]=0.f; d2[nt][1]=0.f; d2[nt][2]=0.f; d2[nt][3]=0.f; }

    const uint32_t ej_u = smem_u32(Ejs);
    const uint32_t sh_u = smem_u32(Sh);
    const int lr = lane & 7, lt = lane >> 3;
    const uint32_t b1_base = ej_u + (uint32_t)lr * (EJH_ST * 2) + (uint32_t)lt * 16;
    const uint32_t a2_base = sh_u
        + (uint32_t)(w * 16 + lr + (lt & 1) * 8) * (SH_ST * 2) + (uint32_t)(lt >> 1) * 16;
    const uint32_t b2_base = ej_u
        + (uint32_t)(lr + (lt & 1) * 8) * (EJH_ST * 2) + (uint32_t)(lt >> 1) * 16;

    for (int j0 = 0; j0 < Nn; j0 += GJT) {
        __syncthreads();
        {
            int j = tid >> 2, qq = tid & 3;
            const float4* src = (const float4*)(eob + (size_t)(j0 + j) * Hh + qq * 16);
            float4 v0 = src[0], v1 = src[1], v2 = src[2], v3 = src[3];
            __half2* dst = (__half2*)(Ejs + j * EJH_ST + qq * 16);
            dst[0] = __floats2half2_rn(v0.x, v0.y);
            dst[1] = __floats2half2_rn(v0.z, v0.w);
            dst[2] = __floats2half2_rn(v1.x, v1.y);
            dst[3] = __floats2half2_rn(v1.z, v1.w);
            dst[4] = __floats2half2_rn(v2.x, v2.y);
            dst[5] = __floats2half2_rn(v2.z, v2.w);
            dst[6] = __floats2half2_rn(v3.x, v3.y);
            dst[7] = __floats2half2_rn(v3.z, v3.w);
        }
        for (int idx = tid; idx < 128 * 16; idx += 256) {
            int i = idx >> 4, jq = idx & 15;
            *(float4*)(CF + i * CF_ST + jq * 4) =
                *(const float4*)(g_coef + (size_t)(i0 + i) * Nn + j0 + jq * 4);
        }
        __syncthreads();

        float d1[8][4];
#pragma unroll
        for (int nt = 0; nt < 8; nt++) { d1[nt][0]=0.f; d1[nt][1]=0.f; d1[nt][2]=0.f; d1[nt][3]=0.f; }
#pragma unroll
        for (int ktp = 0; ktp < 2; ktp++) {
#pragma unroll
            for (int nt = 0; nt < 8; nt++) {
                uint32_t bb[4];
                LDSM4(bb, b1_base + (uint32_t)nt * 8 * (EJH_ST * 2) + (uint32_t)ktp * 64);
                MMA_F16(d1[nt], ae[ktp * 2],     bb);
                MMA_F16(d1[nt], ae[ktp * 2 + 1], bb + 2);
            }
        }
        {
            const float* c0p = CF + (w * 16 + gq) * CF_ST;
            const float* c1p = c0p + 8 * CF_ST;
            __half* s0p = Sh + (w * 16 + gq) * SH_ST;
            __half* s1p = s0p + 8 * SH_ST;
#pragma unroll
            for (int nt = 0; nt < 8; nt++) {
                int cc = nt * 8 + 2 * tq;
                float2 c0 = *(const float2*)(c0p + cc);
                float2 c1 = *(const float2*)(c1p + cc);
                *(__half2*)(s0p + cc) = __floats2half2_rn(d1[nt][0] * c0.x, d1[nt][1] * c0.y);
                *(__half2*)(s1p + cc) = __floats2half2_rn(d1[nt][2] * c1.x, d1[nt][3] * c1.y);
            }
        }
        __syncwarp();

#pragma unroll
        for (int ktj = 0; ktj < 4; ktj++) {
            uint32_t aa[4];
            LDSM4(aa, a2_base + (uint32_t)ktj * 32);
#pragma unroll
            for (int ntp = 0; ntp < 4; ntp++) {
                uint32_t bb[4];
                LDSM4T(bb, b2_base + (uint32_t)ktj * 16 * (EJH_ST * 2) + (uint32_t)ntp * 32);
                MMA_F16(d2[ntp * 2],     aa, bb);
                MMA_F16(d2[ntp * 2 + 1], aa, bb + 2);
            }
        }
    }

    const int i_a = i0 + w * 16 + gq;
    const int i_b = i_a + 8;
    const float inv0 = 1.0f / g_deg[i_a];
    const float inv1 = 1.0f / g_deg[i_b];
    float p0 = 0.f, p1 = 0.f;
#pragma unroll
    for (int kt = 0; kt < 4; kt++) {
        int k0 = kt * 16 + 2 * tq;
        float wa = pred_w[k0], wb = pred_w[k0 + 1];
        float wc = pred_w[k0 + 8], wd = pred_w[k0 + 9];
        float2 v;
        v = __half22float2(*(__half2*)&ae[kt][0]); p0 = fmaf(v.x, wa, fmaf(v.y, wb, p0));
        v = __half22float2(*(__half2*)&ae[kt][2]); p0 = fmaf(v.x, wc, fmaf(v.y, wd, p0));
        v = __half22float2(*(__half2*)&ae[kt][1]); p1 = fmaf(v.x, wa, fmaf(v.y, wb, p1));
        v = __half22float2(*(__half2*)&ae[kt][3]); p1 = fmaf(v.x, wc, fmaf(v.y, wd, p1));
    }
#pragma unroll
    for (int nt = 0; nt < 8; nt++) {
        float wA = pred_w[64 + nt * 8 + 2 * tq];
        float wB = pred_w[64 + nt * 8 + 2 * tq + 1];
        p0 = fmaf(d2[nt][0] * inv0, wA, p0);
        p0 = fmaf(d2[nt][1] * inv0, wB, p0);
        p1 = fmaf(d2[nt][2] * inv1, wA, p1);
        p1 = fmaf(d2[nt][3] * inv1, wB, p1);
    }
    p0 += __shfl_xor_sync(0xffffffffu, p0, 1);
    p0 += __shfl_xor_sync(0xffffffffu, p0, 2);
    p1 += __shfl_xor_sync(0xffffffffu, p1, 1);
    p1 += __shfl_xor_sync(0xffffffffu, p1, 2);
    if (tq == 0) {
        out[(size_t)b * Nn + i_a] = p0 + pred_b[0];
        out[(size_t)b * Nn + i_b] = p1 + pred_b[0];
    }
}

// ---------------------------------------------------------------------------
extern "C" void kernel_launch(void* const* d_in, const int* in_sizes, int n_in,
                              void* d_out, int out_size)
{
    const float* x      = (const float*)d_in[0];
    const float* A      = (const float*)d_in[1];
    const float* Wih    = (const float*)d_in[2];
    const float* Whh    = (const float*)d_in[3];
    const float* bih    = (const float*)d_in[4];
    const float* bhh    = (const float*)d_in[5];
    const float* attn_w = (const float*)d_in[6];
    const float* attn_b = (const float*)d_in[7];
    const float* gnn_w  = (const float*)d_in[8];
    const float* gnn_b  = (const float*)d_in[9];
    const float* pred_w = (const float*)d_in[10];
    const float* pred_b = (const float*)d_in[11];
    float* out = (float*)d_out;

    cudaFuncSetAttribute(lstm_mma_kernel,
                         cudaFuncAttributeMaxDynamicSharedMemorySize, DYN_SMEM);
    cudaFuncSetAttribute(gnn_mma_kernel,
                         cudaFuncAttributeMaxDynamicSharedMemorySize, GNN_SMEM);

    lstm_mma_kernel<<<BN / NSEQ, 256, DYN_SMEM>>>(x, Wih, Whh, bih, bhh,
                                                  attn_w, attn_b, A, gnn_w, gnn_b);
    gnn_mma_kernel<<<dim3(Nn / 128, Bb), 256, GNN_SMEM>>>(pred_w, pred_b, out);
}

// round 16
// speedup vs baseline: 1.5483x; 1.0154x over previous
#include <cuda_runtime.h>
#include <cuda_fp16.h>
#include <cstdint>

#define Bb 32
#define Nn 1024
#define Tt 32
#define Ff 5
#define Hh 64
#define Rr 5
#define BN (Bb*Nn)
#define NSEQ 64

// Scratch
__device__ float g_eold[(size_t)BN * Hh];
__device__ float g_coef[(size_t)Nn * Nn];
__device__ float g_deg[Nn];

__device__ __forceinline__ float tanha(float x) {
    float y; asm("tanh.approx.f32 %0, %1;" : "=f"(y) : "f"(x)); return y;
}
__device__ __forceinline__ float sigma(float x) {
    return fmaf(0.5f, tanha(0.5f * x), 0.5f);
}
__device__ __forceinline__ uint32_t smem_u32(const void* p) {
    uint32_t a;
    asm("{ .reg .u64 t; cvta.to.shared.u64 t, %1; cvt.u32.u64 %0, t; }" : "=r"(a) : "l"(p));
    return a;
}
__device__ __forceinline__ uint32_t pack_h2(float lo, float hi) {
    __half2 h = __floats2half2_rn(lo, hi);
    return *(uint32_t*)&h;
}

// fp16 MMA: D[16,8] += A[16,16] * B[16,8], f32 accum
#define MMA_F16(D, A, B) \
    asm volatile("mma.sync.aligned.m16n8k16.row.col.f32.f16.f16.f32 " \
        "{%0,%1,%2,%3}, {%4,%5,%6,%7}, {%8,%9}, {%0,%1,%2,%3};" \
        : "+f"((D)[0]), "+f"((D)[1]), "+f"((D)[2]), "+f"((D)[3]) \
        : "r"((A)[0]), "r"((A)[1]), "r"((A)[2]), "r"((A)[3]), \
          "r"((B)[0]), "r"((B)[1]))

#define LDSM4(r, addr) \
    asm volatile("ldmatrix.sync.aligned.m8n8.x4.shared.b16 {%0,%1,%2,%3}, [%4];" \
        : "=r"((r)[0]), "=r"((r)[1]), "=r"((r)[2]), "=r"((r)[3]) : "r"(addr))
#define LDSM4T(r, addr) \
    asm volatile("ldmatrix.sync.aligned.m8n8.x4.trans.shared.b16 {%0,%1,%2,%3}, [%4];" \
        : "=r"((r)[0]), "=r"((r)[1]), "=r"((r)[2]), "=r"((r)[3]) : "r"(addr))

// ---- LSTM smem layout (byte offsets); A row = 88 halves ----
#define ASTH   88
#define AS0_B  0
#define AS1_B  11264
#define XH_B   22528
#define SP_B   (XH_B + 20480)
#define WN_B   (SP_B + 2048)
#define AW_B   (WN_B + 256)
#define DYN_SMEM (AW_B + 256)

// ---- GNN smem layout (byte offsets): no S buffer anymore ----
#define GJT    64
#define EJH_ST 88
#define CF_ST  68
#define G_EJ_B 0                           // half [64][88]  = 11264
#define G_CF_B 11264                       // f32 [128][68]  = 34816
#define GNN_SMEM (G_CF_B + 34816)          // 46080 B

// ---------------------------------------------------------------------------
// LSTM phase 1: MMA + fp32 activations (round-12, validated)
// ---------------------------------------------------------------------------
template<int R>
__device__ __forceinline__ void lstm_phase1(
    uint32_t lm_off, const uint32_t (&bf)[4][5][2], float (&c_)[16], float (&hr)[16])
{
#pragma unroll
    for (int mti = 0; mti < 4; mti++) {
        const int mt = (mti + R) & 3;
        float d[4][4];
#pragma unroll
        for (int nt = 0; nt < 4; nt++) {
            d[nt][0] = 0.f; d[nt][1] = 0.f; d[nt][2] = 0.f; d[nt][3] = 0.f;
        }
        const uint32_t mb = lm_off + (uint32_t)mt * 16 * (ASTH * 2);
#pragma unroll
        for (int kt = 0; kt < 5; kt++) {
            uint32_t a[4];
            LDSM4(a, mb + kt * 32);
#pragma unroll
            for (int nt = 0; nt < 4; nt++)
                MMA_F16(d[nt], a, bf[nt][kt]);
        }
#pragma unroll
        for (int e = 0; e < 4; e++) {
            const int p = mt * 4 + e;
            float gi = d[0][e], gf = d[1][e], gg = d[2][e], go = d[3][e];
            float cn = sigma(gf) * c_[p] + sigma(gi) * tanha(gg);
            c_[p] = cn;
            hr[p] = sigma(go) * tanha(cn);
        }
    }
}

// ---------------------------------------------------------------------------
// Kernel 1: fp16 mma.sync LSTM + attention, with fused edge-gate prep.
// (round-15, passing)
// ---------------------------------------------------------------------------
__global__ __launch_bounds__(256, 2) void lstm_mma_kernel(
    const float* __restrict__ x,
    const float* __restrict__ Wih,
    const float* __restrict__ Whh,
    const float* __restrict__ bih,
    const float* __restrict__ bhh,
    const float* __restrict__ attn_w,
    const float* __restrict__ attn_b,
    const float* __restrict__ Ag,
    const float* __restrict__ gnn_w,
    const float* __restrict__ gnn_b)
{
    extern __shared__ char smc[];
    __half* As0 = (__half*)(smc + AS0_B);
    __half* As1 = (__half*)(smc + AS1_B);
    __half* xh  = (__half*)(smc + XH_B);
    float*  SP  = (float*)(smc + SP_B);
    float*  WN  = (float*)(smc + WN_B);
    float*  AW  = (float*)(smc + AW_B);

    const int tid  = threadIdx.x;
    const int w    = tid >> 5, lane = tid & 31;
    const int gq   = lane >> 2;
    const int tq   = lane & 3;
    const size_t seq0 = (size_t)blockIdx.x * NSEQ;

    // ---- fused prep: coef rows r0, r0+1 ----
    {
        const int r0 = blockIdx.x * 2;
        const float gw0 = gnn_w[0], gw1 = gnn_w[1], gw2 = gnn_w[2],
                    gw3 = gnn_w[3], gw4 = gnn_w[4];
        const float gb = gnn_b[0];
        float dl0 = 0.f, dl1 = 0.f;
        for (int j = tid; j < Nn; j += 256) {
            const float* a0 = Ag + ((size_t)r0 * Nn + j) * Rr;
            const float* a1 = a0 + (size_t)Nn * Rr;
            {
                float b0 = a0[0], b1 = a0[1], b2 = a0[2], b3 = a0[3], b4 = a0[4];
                float s = b0 + b1 + b2 + b3 + b4;
                float z = gb + b0 * gw0 + b1 * gw1 + b2 * gw2 + b3 * gw3 + b4 * gw4;
                float wv = z > 0.f ? z : 0.2f * z;
                float m = s > 0.f ? 1.f : 0.f;
                g_coef[(size_t)r0 * Nn + j] = m * wv;
                dl0 += m;
            }
            {
                float b0 = a1[0], b1 = a1[1], b2 = a1[2], b3 = a1[3], b4 = a1[4];
                float s = b0 + b1 + b2 + b3 + b4;
                float z = gb + b0 * gw0 + b1 * gw1 + b2 * gw2 + b3 * gw3 + b4 * gw4;
                float wv = z > 0.f ? z : 0.2f * z;
                float m = s > 0.f ? 1.f : 0.f;
                g_coef[(size_t)(r0 + 1) * Nn + j] = m * wv;
                dl1 += m;
            }
        }
        SP[tid] = dl0;
        SP[256 + tid] = dl1;
    }

    // stage x -> half [t][seq][f]
    {
        const float* xg = x + seq0 * (Tt * Ff);
        for (int i = tid; i < NSEQ * Tt * Ff; i += 256) {
            int s = i / (Tt * Ff);
            int r = i - s * (Tt * Ff);
            int t = r / Ff, f = r - t * Ff;
            xh[(t * NSEQ + s) * Ff + f] = __float2half(xg[i]);
        }
    }
    // zero both A tiles
    {
        uint4 z4 = {0u,0u,0u,0u};
        uint4* ap = (uint4*)As0;
        for (int i = tid; i < 2 * NSEQ * ASTH * 2 / 16; i += 256) ap[i] = z4;
    }
    __syncthreads();

    // ---- prep deg reduction ----
    for (int o = 128; o > 0; o >>= 1) {
        if (tid < o) {
            SP[tid] += SP[tid + o];
            SP[256 + tid] += SP[256 + tid + o];
        }
        __syncthreads();
    }
    if (tid == 0) {
        g_deg[blockIdx.x * 2]     = SP[0];
        g_deg[blockIdx.x * 2 + 1] = SP[256];
    }

    if (tid < NSEQ) {
        As0[tid * ASTH + 69] = __float2half(1.0f);
        As1[tid * ASTH + 69] = __float2half(1.0f);
        const __half* xr = xh + tid * Ff;
#pragma unroll
        for (int f = 0; f < Ff; f++) As0[tid * ASTH + 64 + f] = xr[f];
    }
    if (tid < 64) AW[tid] = attn_w[tid];

    // persistent B fragments
    uint32_t bf[4][5][2];
#pragma unroll
    for (int nt = 0; nt < 4; nt++) {
        const int g = nt * 64 + w * 8 + gq;
        const float bias_g = bih[g] + bhh[g];
#pragma unroll
        for (int kt = 0; kt < 5; kt++) {
#pragma unroll
            for (int hb = 0; hb < 2; hb++) {
                int k0 = kt * 16 + 2 * tq + hb * 8;
                float v0, v1;
                {
                    int k = k0;
                    if (k < 64)       v0 = Whh[g * Hh + k];
                    else if (k < 69)  v0 = Wih[g * Ff + (k - 64)];
                    else if (k == 69) v0 = bias_g;
                    else              v0 = 0.f;
                }
                {
                    int k = k0 + 1;
                    if (k < 64)       v1 = Whh[g * Hh + k];
                    else if (k < 69)  v1 = Wih[g * Ff + (k - 64)];
                    else if (k == 69) v1 = bias_g;
                    else              v1 = 0.f;
                }
                bf[nt][kt][hb] = pack_h2(v0, v1);
            }
        }
    }
    __syncthreads();

    float c_[16], acc_[16], hr[16];
#pragma unroll
    for (int p = 0; p < 16; p++) { c_[p] = 0.f; acc_[p] = 0.f; }
    float Z = 0.f;
    const float ab0 = attn_b[0];
    const float awA = AW[w * 8 + 2 * tq];
    const float awB = AW[w * 8 + 2 * tq + 1];

    const uint32_t as_u = smem_u32(As0);
    const uint32_t lm0 = as_u + (uint32_t)(lane & 15) * (ASTH * 2)
                       + (uint32_t)((lane >> 4) * 16);
    const uint32_t lm1 = lm0 + (AS1_B - AS0_B);
    const int rot = w & 3;

    for (int t = 0; t < Tt; t++) {
        const uint32_t lm_cur = (t & 1) ? lm1 : lm0;
        __half* Awr = (t & 1) ? As0 : As1;

        switch (rot) {
            case 0: lstm_phase1<0>(lm_cur, bf, c_, hr); break;
            case 1: lstm_phase1<1>(lm_cur, bf, c_, hr); break;
            case 2: lstm_phase1<2>(lm_cur, bf, c_, hr); break;
            default: lstm_phase1<3>(lm_cur, bf, c_, hr); break;
        }

#pragma unroll
        for (int mt = 0; mt < 4; mt++) {
#pragma unroll
            for (int pr = 0; pr < 2; pr++) {
                const int p = mt * 4 + pr * 2;
                const int seqr = mt * 16 + gq + pr * 8;
                *(__half2*)(Awr + seqr * ASTH + w * 8 + 2 * tq) =
                    __floats2half2_rn(hr[p], hr[p + 1]);
            }
        }
        if (t < Tt - 1 && tid < NSEQ) {
            const __half* xr = xh + ((t + 1) * NSEQ + tid) * Ff;
#pragma unroll
            for (int f = 0; f < Ff; f++) Awr[tid * ASTH + 64 + f] = xr[f];
        }
#pragma unroll
        for (int mt = 0; mt < 4; mt++) {
#pragma unroll
            for (int pr = 0; pr < 2; pr++) {
                float v = hr[mt * 4 + pr * 2] * awA + hr[mt * 4 + pr * 2 + 1] * awB;
                v += __shfl_xor_sync(0xffffffffu, v, 1);
                v += __shfl_xor_sync(0xffffffffu, v, 2);
                if (tq == 0) SP[w * NSEQ + mt * 16 + gq + pr * 8] = v;
            }
        }
        __syncthreads();
        if (tid < NSEQ) {
            float s = ab0;
#pragma unroll
            for (int ww = 0; ww < 8; ww++) s += SP[ww * NSEQ + tid];
            float e = __expf(tanha(s));
            Z += e;
            WN[tid] = e;
        }
        __syncthreads();
#pragma unroll
        for (int p = 0; p < 16; p++) {
            const int mt = p >> 2, pr = (p >> 1) & 1;
            acc_[p] = fmaf(WN[mt * 16 + gq + pr * 8], hr[p], acc_[p]);
        }
    }

    if (tid < NSEQ) WN[tid] = 1.0f / Z;
    __syncthreads();
#pragma unroll
    for (int p = 0; p < 16; p++) {
        const int mt = p >> 2, pr = (p >> 1) & 1, pc = p & 1;
        const int seqr = mt * 16 + gq + pr * 8;
        const int j = w * 8 + 2 * tq + pc;
        g_eold[(seq0 + seqr) * Hh + j] = acc_[p] * WN[seqr];
    }
}

// ---------------------------------------------------------------------------
// Kernel 2: GNN, fp16 MMA + ldmatrix; S kept entirely in registers.
// MMA1 accumulator layout == MMA2 A-operand layout (per-warp rows), so
// coef-scaled d1 packs feed MMA2 directly. No Sh buffer, no a2 ldmatrix.
// ---------------------------------------------------------------------------
__global__ __launch_bounds__(256, 2) void gnn_mma_kernel(
    const float* __restrict__ pred_w,
    const float* __restrict__ pred_b,
    float* __restrict__ out)
{
    extern __shared__ char gsc[];
    __half* Ejs = (__half*)(gsc + G_EJ_B);
    float*  CF  = (float*)(gsc + G_CF_B);

    const int tid = threadIdx.x;
    const int w = tid >> 5, lane = tid & 31;
    const int gq = lane >> 2, tq = lane & 3;
    const int b  = blockIdx.y;
    const int i0 = blockIdx.x * 128;
    const float* eob = g_eold + (size_t)b * Nn * Hh;

    uint32_t ae[4][4];
    {
        const float* r0 = eob + (size_t)(i0 + w * 16 + gq) * Hh;
        const float* r1 = r0 + 8 * Hh;
#pragma unroll
        for (int kt = 0; kt < 4; kt++) {
            int k0 = kt * 16 + 2 * tq;
            ae[kt][0] = pack_h2(r0[k0],     r0[k0 + 1]);
            ae[kt][1] = pack_h2(r1[k0],     r1[k0 + 1]);
            ae[kt][2] = pack_h2(r0[k0 + 8], r0[k0 + 9]);
            ae[kt][3] = pack_h2(r1[k0 + 8], r1[k0 + 9]);
        }
    }
    float d2[8][4];
#pragma unroll
    for (int nt = 0; nt < 8; nt++) { d2[nt][0]=0.f; d2[nt][1]=0.f; d2[nt][2]=0.f; d2[nt][3]=0.f; }

    const uint32_t ej_u = smem_u32(Ejs);
    const int lr = lane & 7, lt = lane >> 3;
    const uint32_t b1_base = ej_u + (uint32_t)lr * (EJH_ST * 2) + (uint32_t)lt * 16;
    const uint32_t b2_base = ej_u
        + (uint32_t)(lr + (lt & 1) * 8) * (EJH_ST * 2) + (uint32_t)(lt >> 1) * 16;

    for (int j0 = 0; j0 < Nn; j0 += GJT) {
        __syncthreads();
        // stage Ej -> fp16 [64][88], vectorized STS.128
        {
            int j = tid >> 2, qq = tid & 3;
            const float4* src = (const float4*)(eob + (size_t)(j0 + j) * Hh + qq * 16);
            float4 v0 = src[0], v1 = src[1], v2 = src[2], v3 = src[3];
            uint4 o1, o2;
            o1.x = pack_h2(v0.x, v0.y); o1.y = pack_h2(v0.z, v0.w);
            o1.z = pack_h2(v1.x, v1.y); o1.w = pack_h2(v1.z, v1.w);
            o2.x = pack_h2(v2.x, v2.y); o2.y = pack_h2(v2.z, v2.w);
            o2.z = pack_h2(v3.x, v3.y); o2.w = pack_h2(v3.z, v3.w);
            uint4* dst = (uint4*)(Ejs + j * EJH_ST + qq * 16);
            dst[0] = o1;
            dst[1] = o2;
        }
        // stage coef fp32 [128][68]
        for (int idx = tid; idx < 128 * 16; idx += 256) {
            int i = idx >> 4, jq = idx & 15;
            *(float4*)(CF + i * CF_ST + jq * 4) =
                *(const float4*)(g_coef + (size_t)(i0 + i) * Nn + j0 + jq * 4);
        }
        __syncthreads();

        // ---- MMA1: S[16 i][64 j] in registers ----
        float d1[8][4];
#pragma unroll
        for (int nt = 0; nt < 8; nt++) { d1[nt][0]=0.f; d1[nt][1]=0.f; d1[nt][2]=0.f; d1[nt][3]=0.f; }
#pragma unroll
        for (int ktp = 0; ktp < 2; ktp++) {
#pragma unroll
            for (int nt = 0; nt < 8; nt++) {
                uint32_t bb[4];
                LDSM4(bb, b1_base + (uint32_t)nt * 8 * (EJH_ST * 2) + (uint32_t)ktp * 64);
                MMA_F16(d1[nt], ae[ktp * 2],     bb);
                MMA_F16(d1[nt], ae[ktp * 2 + 1], bb + 2);
            }
        }
        // ---- apply coef in registers, pack to MMA2 A-fragments ----
        uint32_t a2f[8][2];
        {
            const float* c0p = CF + (w * 16 + gq) * CF_ST;
            const float* c1p = c0p + 8 * CF_ST;
#pragma unroll
            for (int nt = 0; nt < 8; nt++) {
                int cc = nt * 8 + 2 * tq;
                float2 c0 = *(const float2*)(c0p + cc);
                float2 c1 = *(const float2*)(c1p + cc);
                a2f[nt][0] = pack_h2(d1[nt][0] * c0.x, d1[nt][1] * c0.y);   // row gq
                a2f[nt][1] = pack_h2(d1[nt][2] * c1.x, d1[nt][3] * c1.y);   // row gq+8
            }
        }

        // ---- MMA2: e_new[16 i][64 h] += S x Ej ; A from registers ----
#pragma unroll
        for (int ktj = 0; ktj < 4; ktj++) {
            uint32_t aa[4];
            aa[0] = a2f[2 * ktj][0];       // (row gq,   k 2tq..)
            aa[1] = a2f[2 * ktj][1];       // (row gq+8, k 2tq..)
            aa[2] = a2f[2 * ktj + 1][0];   // (row gq,   k 2tq+8..)
            aa[3] = a2f[2 * ktj + 1][1];   // (row gq+8, k 2tq+8..)
#pragma unroll
            for (int ntp = 0; ntp < 4; ntp++) {
                uint32_t bb[4];
                LDSM4T(bb, b2_base + (uint32_t)ktj * 16 * (EJH_ST * 2) + (uint32_t)ntp * 32);
                MMA_F16(d2[ntp * 2],     aa, bb);
                MMA_F16(d2[ntp * 2 + 1], aa, bb + 2);
            }
        }
    }

    // ---- fused pred head ----
    const int i_a = i0 + w * 16 + gq;
    const int i_b = i_a + 8;
    const float inv0 = 1.0f / g_deg[i_a];
    const float inv1 = 1.0f / g_deg[i_b];
    float p0 = 0.f, p1 = 0.f;
#pragma unroll
    for (int kt = 0; kt < 4; kt++) {
        int k0 = kt * 16 + 2 * tq;
        float wa = pred_w[k0], wb = pred_w[k0 + 1];
        float wc = pred_w[k0 + 8], wd = pred_w[k0 + 9];
        float2 v;
        v = __half22float2(*(__half2*)&ae[kt][0]); p0 = fmaf(v.x, wa, fmaf(v.y, wb, p0));
        v = __half22float2(*(__half2*)&ae[kt][2]); p0 = fmaf(v.x, wc, fmaf(v.y, wd, p0));
        v = __half22float2(*(__half2*)&ae[kt][1]); p1 = fmaf(v.x, wa, fmaf(v.y, wb, p1));
        v = __half22float2(*(__half2*)&ae[kt][3]); p1 = fmaf(v.x, wc, fmaf(v.y, wd, p1));
    }
#pragma unroll
    for (int nt = 0; nt < 8; nt++) {
        float wA = pred_w[64 + nt * 8 + 2 * tq];
        float wB = pred_w[64 + nt * 8 + 2 * tq + 1];
        p0 = fmaf(d2[nt][0] * inv0, wA, p0);
        p0 = fmaf(d2[nt][1] * inv0, wB, p0);
        p1 = fmaf(d2[nt][2] * inv1, wA, p1);
        p1 = fmaf(d2[nt][3] * inv1, wB, p1);
    }
    p0 += __shfl_xor_sync(0xffffffffu, p0, 1);
    p0 += __shfl_xor_sync(0xffffffffu, p0, 2);
    p1 += __shfl_xor_sync(0xffffffffu, p1, 1);
    p1 += __shfl_xor_sync(0xffffffffu, p1, 2);
    if (tq == 0) {
        out[(size_t)b * Nn + i_a] = p0 + pred_b[0];
        out[(size_t)b * Nn + i_b] = p1 + pred_b[0];
    }
}

// ---------------------------------------------------------------------------
extern "C" void kernel_launch(void* const* d_in, const int* in_sizes, int n_in,
                              void* d_out, int out_size)
{
    const float* x      = (const float*)d_in[0];
    const float* A      = (const float*)d_in[1];
    const float* Wih    = (const float*)d_in[2];
    const float* Whh    = (const float*)d_in[3];
    const float* bih    = (const float*)d_in[4];
    const float* bhh    = (const float*)d_in[5];
    const float* attn_w = (const float*)d_in[6];
    const float* attn_b = (const float*)d_in[7];
    const float* gnn_w  = (const float*)d_in[8];
    const float* gnn_b  = (const float*)d_in[9];
    const float* pred_w = (const float*)d_in[10];
    const float* pred_b = (const float*)d_in[11];
    float* out = (float*)d_out;

    cudaFuncSetAttribute(lstm_mma_kernel,
                         cudaFuncAttributeMaxDynamicSharedMemorySize, DYN_SMEM);
    cudaFuncSetAttribute(gnn_mma_kernel,
                         cudaFuncAttributeMaxDynamicSharedMemorySize, GNN_SMEM);

    lstm_mma_kernel<<<BN / NSEQ, 256, DYN_SMEM>>>(x, Wih, Whh, bih, bhh,
                                                  attn_w, attn_b, A, gnn_w, gnn_b);
    gnn_mma_kernel<<<dim3(Nn / 128, Bb), 256, GNN_SMEM>>>(pred_w, pred_b, out);
}

// round 17
// speedup vs baseline: 1.6408x; 1.0597x over previous
#include <cuda_runtime.h>
#include <cuda_fp16.h>
#include <cstdint>

#define Bb 32
#define Nn 1024
#define Tt 32
#define Ff 5
#define Hh 64
#define Rr 5
#define BN (Bb*Nn)
#define NSEQ 64

// Scratch
__device__ __half g_eold_h[(size_t)BN * Hh];   // fp16 e_old (rounded once at LSTM store)
__device__ float  g_coef[(size_t)Nn * Nn];
__device__ float  g_deg[Nn];

__device__ __forceinline__ float tanha(float x) {
    float y; asm("tanh.approx.f32 %0, %1;" : "=f"(y) : "f"(x)); return y;
}
__device__ __forceinline__ float sigma(float x) {
    return fmaf(0.5f, tanha(0.5f * x), 0.5f);
}
__device__ __forceinline__ uint32_t smem_u32(const void* p) {
    uint32_t a;
    asm("{ .reg .u64 t; cvta.to.shared.u64 t, %1; cvt.u32.u64 %0, t; }" : "=r"(a) : "l"(p));
    return a;
}
__device__ __forceinline__ uint32_t pack_h2(float lo, float hi) {
    __half2 h = __floats2half2_rn(lo, hi);
    return *(uint32_t*)&h;
}

// fp16 MMA: D[16,8] += A[16,16] * B[16,8], f32 accum
#define MMA_F16(D, A, B) \
    asm volatile("mma.sync.aligned.m16n8k16.row.col.f32.f16.f16.f32 " \
        "{%0,%1,%2,%3}, {%4,%5,%6,%7}, {%8,%9}, {%0,%1,%2,%3};" \
        : "+f"((D)[0]), "+f"((D)[1]), "+f"((D)[2]), "+f"((D)[3]) \
        : "r"((A)[0]), "r"((A)[1]), "r"((A)[2]), "r"((A)[3]), \
          "r"((B)[0]), "r"((B)[1]))

#define LDSM4(r, addr) \
    asm volatile("ldmatrix.sync.aligned.m8n8.x4.shared.b16 {%0,%1,%2,%3}, [%4];" \
        : "=r"((r)[0]), "=r"((r)[1]), "=r"((r)[2]), "=r"((r)[3]) : "r"(addr))
#define LDSM4T(r, addr) \
    asm volatile("ldmatrix.sync.aligned.m8n8.x4.trans.shared.b16 {%0,%1,%2,%3}, [%4];" \
        : "=r"((r)[0]), "=r"((r)[1]), "=r"((r)[2]), "=r"((r)[3]) : "r"(addr))

// cp.async (LDGSTS) helpers
#define CP_ASYNC16(dst, src) \
    asm volatile("cp.async.cg.shared.global [%0], [%1], 16;" \
        :: "r"(dst), "l"(src) : "memory")
#define CP_COMMIT() asm volatile("cp.async.commit_group;" ::: "memory")
#define CP_WAIT1()  asm volatile("cp.async.wait_group 1;" ::: "memory")
#define CP_WAIT0()  asm volatile("cp.async.wait_group 0;" ::: "memory")

// ---- LSTM smem layout (byte offsets); A row = 88 halves ----
#define ASTH   88
#define AS0_B  0
#define AS1_B  11264
#define XH_B   22528
#define SP_B   (XH_B + 20480)
#define WN_B   (SP_B + 2048)
#define AW_B   (WN_B + 256)
#define DYN_SMEM (AW_B + 256)

// ---- GNN smem layout: double-buffered [Ej half 64x88 | CF f32 128x68] ----
#define GJT    64
#define EJH_ST 88
#define CF_ST  68
#define GBUF_B 46080                        // 11264 + 34816
#define GNN_SMEM (2 * GBUF_B)               // 92160 B

// ---------------------------------------------------------------------------
// LSTM phase 1: MMA + fp32 activations (round-12, validated)
// ---------------------------------------------------------------------------
template<int R>
__device__ __forceinline__ void lstm_phase1(
    uint32_t lm_off, const uint32_t (&bf)[4][5][2], float (&c_)[16], float (&hr)[16])
{
#pragma unroll
    for (int mti = 0; mti < 4; mti++) {
        const int mt = (mti + R) & 3;
        float d[4][4];
#pragma unroll
        for (int nt = 0; nt < 4; nt++) {
            d[nt][0] = 0.f; d[nt][1] = 0.f; d[nt][2] = 0.f; d[nt][3] = 0.f;
        }
        const uint32_t mb = lm_off + (uint32_t)mt * 16 * (ASTH * 2);
#pragma unroll
        for (int kt = 0; kt < 5; kt++) {
            uint32_t a[4];
            LDSM4(a, mb + kt * 32);
#pragma unroll
            for (int nt = 0; nt < 4; nt++)
                MMA_F16(d[nt], a, bf[nt][kt]);
        }
#pragma unroll
        for (int e = 0; e < 4; e++) {
            const int p = mt * 4 + e;
            float gi = d[0][e], gf = d[1][e], gg = d[2][e], go = d[3][e];
            float cn = sigma(gf) * c_[p] + sigma(gi) * tanha(gg);
            c_[p] = cn;
            hr[p] = sigma(go) * tanha(cn);
        }
    }
}

// ---------------------------------------------------------------------------
// Kernel 1: fp16 mma.sync LSTM + attention, with fused edge-gate prep.
// (round-15 structure; e_old now stored as fp16, same rounding)
// ---------------------------------------------------------------------------
__global__ __launch_bounds__(256, 2) void lstm_mma_kernel(
    const float* __restrict__ x,
    const float* __restrict__ Wih,
    const float* __restrict__ Whh,
    const float* __restrict__ bih,
    const float* __restrict__ bhh,
    const float* __restrict__ attn_w,
    const float* __restrict__ attn_b,
    const float* __restrict__ Ag,
    const float* __restrict__ gnn_w,
    const float* __restrict__ gnn_b)
{
    extern __shared__ char smc[];
    __half* As0 = (__half*)(smc + AS0_B);
    __half* As1 = (__half*)(smc + AS1_B);
    __half* xh  = (__half*)(smc + XH_B);
    float*  SP  = (float*)(smc + SP_B);
    float*  WN  = (float*)(smc + WN_B);
    float*  AW  = (float*)(smc + AW_B);

    const int tid  = threadIdx.x;
    const int w    = tid >> 5, lane = tid & 31;
    const int gq   = lane >> 2;
    const int tq   = lane & 3;
    const size_t seq0 = (size_t)blockIdx.x * NSEQ;

    // ---- fused prep: coef rows r0, r0+1 ----
    {
        const int r0 = blockIdx.x * 2;
        const float gw0 = gnn_w[0], gw1 = gnn_w[1], gw2 = gnn_w[2],
                    gw3 = gnn_w[3], gw4 = gnn_w[4];
        const float gb = gnn_b[0];
        float dl0 = 0.f, dl1 = 0.f;
        for (int j = tid; j < Nn; j += 256) {
            const float* a0 = Ag + ((size_t)r0 * Nn + j) * Rr;
            const float* a1 = a0 + (size_t)Nn * Rr;
            {
                float b0 = a0[0], b1 = a0[1], b2 = a0[2], b3 = a0[3], b4 = a0[4];
                float s = b0 + b1 + b2 + b3 + b4;
                float z = gb + b0 * gw0 + b1 * gw1 + b2 * gw2 + b3 * gw3 + b4 * gw4;
                float wv = z > 0.f ? z : 0.2f * z;
                float m = s > 0.f ? 1.f : 0.f;
                g_coef[(size_t)r0 * Nn + j] = m * wv;
                dl0 += m;
            }
            {
                float b0 = a1[0], b1 = a1[1], b2 = a1[2], b3 = a1[3], b4 = a1[4];
                float s = b0 + b1 + b2 + b3 + b4;
                float z = gb + b0 * gw0 + b1 * gw1 + b2 * gw2 + b3 * gw3 + b4 * gw4;
                float wv = z > 0.f ? z : 0.2f * z;
                float m = s > 0.f ? 1.f : 0.f;
                g_coef[(size_t)(r0 + 1) * Nn + j] = m * wv;
                dl1 += m;
            }
        }
        SP[tid] = dl0;
        SP[256 + tid] = dl1;
    }

    // stage x -> half [t][seq][f]
    {
        const float* xg = x + seq0 * (Tt * Ff);
        for (int i = tid; i < NSEQ * Tt * Ff; i += 256) {
            int s = i / (Tt * Ff);
            int r = i - s * (Tt * Ff);
            int t = r / Ff, f = r - t * Ff;
            xh[(t * NSEQ + s) * Ff + f] = __float2half(xg[i]);
        }
    }
    // zero both A tiles
    {
        uint4 z4 = {0u,0u,0u,0u};
        uint4* ap = (uint4*)As0;
        for (int i = tid; i < 2 * NSEQ * ASTH * 2 / 16; i += 256) ap[i] = z4;
    }
    __syncthreads();

    // ---- prep deg reduction ----
    for (int o = 128; o > 0; o >>= 1) {
        if (tid < o) {
            SP[tid] += SP[tid + o];
            SP[256 + tid] += SP[256 + tid + o];
        }
        __syncthreads();
    }
    if (tid == 0) {
        g_deg[blockIdx.x * 2]     = SP[0];
        g_deg[blockIdx.x * 2 + 1] = SP[256];
    }

    if (tid < NSEQ) {
        As0[tid * ASTH + 69] = __float2half(1.0f);
        As1[tid * ASTH + 69] = __float2half(1.0f);
        const __half* xr = xh + tid * Ff;
#pragma unroll
        for (int f = 0; f < Ff; f++) As0[tid * ASTH + 64 + f] = xr[f];
    }
    if (tid < 64) AW[tid] = attn_w[tid];

    // persistent B fragments
    uint32_t bf[4][5][2];
#pragma unroll
    for (int nt = 0; nt < 4; nt++) {
        const int g = nt * 64 + w * 8 + gq;
        const float bias_g = bih[g] + bhh[g];
#pragma unroll
        for (int kt = 0; kt < 5; kt++) {
#pragma unroll
            for (int hb = 0; hb < 2; hb++) {
                int k0 = kt * 16 + 2 * tq + hb * 8;
                float v0, v1;
                {
                    int k = k0;
                    if (k < 64)       v0 = Whh[g * Hh + k];
                    else if (k < 69)  v0 = Wih[g * Ff + (k - 64)];
                    else if (k == 69) v0 = bias_g;
                    else              v0 = 0.f;
                }
                {
                    int k = k0 + 1;
                    if (k < 64)       v1 = Whh[g * Hh + k];
                    else if (k < 69)  v1 = Wih[g * Ff + (k - 64)];
                    else if (k == 69) v1 = bias_g;
                    else              v1 = 0.f;
                }
                bf[nt][kt][hb] = pack_h2(v0, v1);
            }
        }
    }
    __syncthreads();

    float c_[16], acc_[16], hr[16];
#pragma unroll
    for (int p = 0; p < 16; p++) { c_[p] = 0.f; acc_[p] = 0.f; }
    float Z = 0.f;
    const float ab0 = attn_b[0];
    const float awA = AW[w * 8 + 2 * tq];
    const float awB = AW[w * 8 + 2 * tq + 1];

    const uint32_t as_u = smem_u32(As0);
    const uint32_t lm0 = as_u + (uint32_t)(lane & 15) * (ASTH * 2)
                       + (uint32_t)((lane >> 4) * 16);
    const uint32_t lm1 = lm0 + (AS1_B - AS0_B);
    const int rot = w & 3;

    for (int t = 0; t < Tt; t++) {
        const uint32_t lm_cur = (t & 1) ? lm1 : lm0;
        __half* Awr = (t & 1) ? As0 : As1;

        switch (rot) {
            case 0: lstm_phase1<0>(lm_cur, bf, c_, hr); break;
            case 1: lstm_phase1<1>(lm_cur, bf, c_, hr); break;
            case 2: lstm_phase1<2>(lm_cur, bf, c_, hr); break;
            default: lstm_phase1<3>(lm_cur, bf, c_, hr); break;
        }

#pragma unroll
        for (int mt = 0; mt < 4; mt++) {
#pragma unroll
            for (int pr = 0; pr < 2; pr++) {
                const int p = mt * 4 + pr * 2;
                const int seqr = mt * 16 + gq + pr * 8;
                *(__half2*)(Awr + seqr * ASTH + w * 8 + 2 * tq) =
                    __floats2half2_rn(hr[p], hr[p + 1]);
            }
        }
        if (t < Tt - 1 && tid < NSEQ) {
            const __half* xr = xh + ((t + 1) * NSEQ + tid) * Ff;
#pragma unroll
            for (int f = 0; f < Ff; f++) Awr[tid * ASTH + 64 + f] = xr[f];
        }
#pragma unroll
        for (int mt = 0; mt < 4; mt++) {
#pragma unroll
            for (int pr = 0; pr < 2; pr++) {
                float v = hr[mt * 4 + pr * 2] * awA + hr[mt * 4 + pr * 2 + 1] * awB;
                v += __shfl_xor_sync(0xffffffffu, v, 1);
                v += __shfl_xor_sync(0xffffffffu, v, 2);
                if (tq == 0) SP[w * NSEQ + mt * 16 + gq + pr * 8] = v;
            }
        }
        __syncthreads();
        if (tid < NSEQ) {
            float s = ab0;
#pragma unroll
            for (int ww = 0; ww < 8; ww++) s += SP[ww * NSEQ + tid];
            float e = __expf(tanha(s));
            Z += e;
            WN[tid] = e;
        }
        __syncthreads();
#pragma unroll
        for (int p = 0; p < 16; p++) {
            const int mt = p >> 2, pr = (p >> 1) & 1;
            acc_[p] = fmaf(WN[mt * 16 + gq + pr * 8], hr[p], acc_[p]);
        }
    }

    if (tid < NSEQ) WN[tid] = 1.0f / Z;
    __syncthreads();
    // e_old -> fp16 global (same _rn rounding the GNN applied before)
#pragma unroll
    for (int mt = 0; mt < 4; mt++) {
#pragma unroll
        for (int pr = 0; pr < 2; pr++) {
            const int p = mt * 4 + pr * 2;
            const int seqr = mt * 16 + gq + pr * 8;
            const float iz = WN[seqr];
            *(__half2*)(g_eold_h + (seq0 + seqr) * Hh + w * 8 + 2 * tq) =
                __floats2half2_rn(acc_[p] * iz, acc_[p + 1] * iz);
        }
    }
}

// ---------------------------------------------------------------------------
// Kernel 2: GNN, fp16 MMA + ldmatrix, register-S, cp.async double-buffered
// staging of Ej (fp16 copy) and coef (fp32).
// ---------------------------------------------------------------------------
__global__ __launch_bounds__(256, 2) void gnn_mma_kernel(
    const float* __restrict__ pred_w,
    const float* __restrict__ pred_b,
    float* __restrict__ out)
{
    extern __shared__ char gsc[];

    const int tid = threadIdx.x;
    const int w = tid >> 5, lane = tid & 31;
    const int gq = lane >> 2, tq = lane & 3;
    const int b  = blockIdx.y;
    const int i0 = blockIdx.x * 128;
    const __half* eobh = g_eold_h + (size_t)b * Nn * Hh;

    // Ei fp16 A-frags directly from fp16 e_old
    uint32_t ae[4][4];
    {
        const __half* r0 = eobh + (size_t)(i0 + w * 16 + gq) * Hh;
        const __half* r1 = r0 + 8 * Hh;
#pragma unroll
        for (int kt = 0; kt < 4; kt++) {
            int k0 = kt * 16 + 2 * tq;
            ae[kt][0] = *(const uint32_t*)(r0 + k0);
            ae[kt][1] = *(const uint32_t*)(r1 + k0);
            ae[kt][2] = *(const uint32_t*)(r0 + k0 + 8);
            ae[kt][3] = *(const uint32_t*)(r1 + k0 + 8);
        }
    }
    float d2[8][4];
#pragma unroll
    for (int nt = 0; nt < 8; nt++) { d2[nt][0]=0.f; d2[nt][1]=0.f; d2[nt][2]=0.f; d2[nt][3]=0.f; }

    const uint32_t sm_u = smem_u32(gsc);
    const int lr = lane & 7, lt = lane >> 3;
    // lane offsets within a buffer
    const uint32_t b1_off = (uint32_t)lr * (EJH_ST * 2) + (uint32_t)lt * 16;
    const uint32_t b2_off = (uint32_t)(lr + (lt & 1) * 8) * (EJH_ST * 2)
                          + (uint32_t)(lt >> 1) * 16;

    // staging: thread's fixed assignments
    const int sj = tid >> 2, sq = tid & 3;          // Ej: row sj, quarter sq (32B)
    const __half* ej_src_base = eobh + (size_t)sj * Hh + sq * 16;
    const uint32_t ej_dst_off = (uint32_t)(sj * EJH_ST + sq * 16) * 2;

#define STAGE_TILE(JT, BUF) do { \
        const uint32_t bufb = sm_u + (uint32_t)(BUF) * GBUF_B; \
        const __half* esrc = ej_src_base + (size_t)(JT) * GJT * Hh; \
        uint32_t edst = bufb + ej_dst_off; \
        CP_ASYNC16(edst, esrc); \
        CP_ASYNC16(edst + 16, esrc + 8); \
        const uint32_t cfb = bufb + 11264; \
        _Pragma("unroll") \
        for (int it = 0; it < 8; it++) { \
            int idx = tid + it * 256; \
            int ii = idx >> 4, jq = idx & 15; \
            const float* csrc = g_coef + (size_t)(i0 + ii) * Nn + (JT) * GJT + jq * 4; \
            CP_ASYNC16(cfb + (uint32_t)(ii * CF_ST + jq * 4) * 4, csrc); \
        } \
    } while (0)

    STAGE_TILE(0, 0);
    CP_COMMIT();

    for (int jt = 0; jt < 16; jt++) {
        if (jt < 15) {
            STAGE_TILE(jt + 1, (jt + 1) & 1);
            CP_COMMIT();
            CP_WAIT1();
        } else {
            CP_WAIT0();
        }
        __syncthreads();   // tile jt staged + visible

        const uint32_t bufb = sm_u + (uint32_t)(jt & 1) * GBUF_B;
        const uint32_t b1_base = bufb + b1_off;
        const uint32_t b2_base = bufb + b2_off;
        const float* CF = (const float*)(gsc + (jt & 1) * GBUF_B + 11264);

        // ---- MMA1: S[16 i][64 j] in registers ----
        float d1[8][4];
#pragma unroll
        for (int nt = 0; nt < 8; nt++) { d1[nt][0]=0.f; d1[nt][1]=0.f; d1[nt][2]=0.f; d1[nt][3]=0.f; }
#pragma unroll
        for (int ktp = 0; ktp < 2; ktp++) {
#pragma unroll
            for (int nt = 0; nt < 8; nt++) {
                uint32_t bb[4];
                LDSM4(bb, b1_base + (uint32_t)nt * 8 * (EJH_ST * 2) + (uint32_t)ktp * 64);
                MMA_F16(d1[nt], ae[ktp * 2],     bb);
                MMA_F16(d1[nt], ae[ktp * 2 + 1], bb + 2);
            }
        }
        // ---- apply coef in registers, pack to MMA2 A-fragments ----
        uint32_t a2f[8][2];
        {
            const float* c0p = CF + (w * 16 + gq) * CF_ST;
            const float* c1p = c0p + 8 * CF_ST;
#pragma unroll
            for (int nt = 0; nt < 8; nt++) {
                int cc = nt * 8 + 2 * tq;
                float2 c0 = *(const float2*)(c0p + cc);
                float2 c1 = *(const float2*)(c1p + cc);
                a2f[nt][0] = pack_h2(d1[nt][0] * c0.x, d1[nt][1] * c0.y);
                a2f[nt][1] = pack_h2(d1[nt][2] * c1.x, d1[nt][3] * c1.y);
            }
        }

        // ---- MMA2: e_new[16 i][64 h] += S x Ej ----
#pragma unroll
        for (int ktj = 0; ktj < 4; ktj++) {
            uint32_t aa[4];
            aa[0] = a2f[2 * ktj][0];
            aa[1] = a2f[2 * ktj][1];
            aa[2] = a2f[2 * ktj + 1][0];
            aa[3] = a2f[2 * ktj + 1][1];
#pragma unroll
            for (int ntp = 0; ntp < 4; ntp++) {
                uint32_t bb[4];
                LDSM4T(bb, b2_base + (uint32_t)ktj * 16 * (EJH_ST * 2) + (uint32_t)ntp * 32);
                MMA_F16(d2[ntp * 2],     aa, bb);
                MMA_F16(d2[ntp * 2 + 1], aa, bb + 2);
            }
        }
        __syncthreads();   // all warps done with this buffer (re-staged at jt+2)
    }

    // ---- fused pred head ----
    const int i_a = i0 + w * 16 + gq;
    const int i_b = i_a + 8;
    const float inv0 = 1.0f / g_deg[i_a];
    const float inv1 = 1.0f / g_deg[i_b];
    float p0 = 0.f, p1 = 0.f;
#pragma unroll
    for (int kt = 0; kt < 4; kt++) {
        int k0 = kt * 16 + 2 * tq;
        float wa = pred_w[k0], wb = pred_w[k0 + 1];
        float wc = pred_w[k0 + 8], wd = pred_w[k0 + 9];
        float2 v;
        v = __half22float2(*(__half2*)&ae[kt][0]); p0 = fmaf(v.x, wa, fmaf(v.y, wb, p0));
        v = __half22float2(*(__half2*)&ae[kt][2]); p0 = fmaf(v.x, wc, fmaf(v.y, wd, p0));
        v = __half22float2(*(__half2*)&ae[kt][1]); p1 = fmaf(v.x, wa, fmaf(v.y, wb, p1));
        v = __half22float2(*(__half2*)&ae[kt][3]); p1 = fmaf(v.x, wc, fmaf(v.y, wd, p1));
    }
#pragma unroll
    for (int nt = 0; nt < 8; nt++) {
        float wA = pred_w[64 + nt * 8 + 2 * tq];
        float wB = pred_w[64 + nt * 8 + 2 * tq + 1];
        p0 = fmaf(d2[nt][0] * inv0, wA, p0);
        p0 = fmaf(d2[nt][1] * inv0, wB, p0);
        p1 = fmaf(d2[nt][2] * inv1, wA, p1);
        p1 = fmaf(d2[nt][3] * inv1, wB, p1);
    }
    p0 += __shfl_xor_sync(0xffffffffu, p0, 1);
    p0 += __shfl_xor_sync(0xffffffffu, p0, 2);
    p1 += __shfl_xor_sync(0xffffffffu, p1, 1);
    p1 += __shfl_xor_sync(0xffffffffu, p1, 2);
    if (tq == 0) {
        out[(size_t)b * Nn + i_a] = p0 + pred_b[0];
        out[(size_t)b * Nn + i_b] = p1 + pred_b[0];
    }
}

// ---------------------------------------------------------------------------
extern "C" void kernel_launch(void* const* d_in, const int* in_sizes, int n_in,
                              void* d_out, int out_size)
{
    const float* x      = (const float*)d_in[0];
    const float* A      = (const float*)d_in[1];
    const float* Wih    = (const float*)d_in[2];
    const float* Whh    = (const float*)d_in[3];
    const float* bih    = (const float*)d_in[4];
    const float* bhh    = (const float*)d_in[5];
    const float* attn_w = (const float*)d_in[6];
    const float* attn_b = (const float*)d_in[7];
    const float* gnn_w  = (const float*)d_in[8];
    const float* gnn_b  = (const float*)d_in[9];
    const float* pred_w = (const float*)d_in[10];
    const float* pred_b = (const float*)d_in[11];
    float* out = (float*)d_out;

    cudaFuncSetAttribute(lstm_mma_kernel,
                         cudaFuncAttributeMaxDynamicSharedMemorySize, DYN_SMEM);
    cudaFuncSetAttribute(gnn_mma_kernel,
                         cudaFuncAttributeMaxDynamicSharedMemorySize, GNN_SMEM);

    lstm_mma_kernel<<<BN / NSEQ, 256, DYN_SMEM>>>(x, Wih, Whh, bih, bhh,
                                                  attn_w, attn_b, A, gnn_w, gnn_b);
    gnn_mma_kernel<<<dim3(Nn / 128, Bb), 256, GNN_SMEM>>>(pred_w, pred_b, out);
}